// round 1
// baseline (speedup 1.0000x reference)
#include <cuda_runtime.h>
#include <cuda_bf16.h>

// Problem constants (from reference): B=4, N=2048, F_in=128, F_out=64, H=4
#define Bx 4
#define Nx 2048
#define FIN 128
#define FOUT 64
#define Hx 4
#define ALPHA 0.2f

#define M_TILE 16
#define J_TILE 32

// Scratch: ht [b][n][h][f] (f contiguous), e_src/e_dst [b][n][h]
__device__ float g_ht[Bx * Nx * Hx * FOUT];     // 8 MB
__device__ float g_esrc[Bx * Nx * Hx];
__device__ float g_edst[Bx * Nx * Hx];

// ---------------------------------------------------------------------------
// Kernel 1: per (b,n) row: ht = h @ W (all 4 heads), plus e_src/e_dst dots.
// 256 threads: thread t -> head = t/64, f = t%64.
// ---------------------------------------------------------------------------
__global__ __launch_bounds__(256) void gat_proj_kernel(
    const float* __restrict__ h,   // [B][N][FIN]
    const float* __restrict__ W,   // [H][FIN][FOUT]
    const float* __restrict__ a)   // [H][2*FOUT]
{
    __shared__ float h_s[FIN];
    __shared__ float red_src[Hx][2];
    __shared__ float red_dst[Hx][2];

    const int bid = blockIdx.x;          // b*N + n
    const int t = threadIdx.x;
    const int hh = t >> 6;               // head
    const int f  = t & 63;

    if (t < FIN) h_s[t] = h[(size_t)bid * FIN + t];
    __syncthreads();

    float acc = 0.f;
    const float* Wp = W + (hh * FIN) * FOUT + f;
#pragma unroll 8
    for (int i = 0; i < FIN; i++) {
        acc += h_s[i] * Wp[i * FOUT];
    }
    g_ht[(size_t)bid * (Hx * FOUT) + t] = acc;

    // e_src/e_dst reductions over f (64 lanes = 2 warps per head)
    float ps = acc * a[hh * (2 * FOUT) + f];
    float pd = acc * a[hh * (2 * FOUT) + FOUT + f];
#pragma unroll
    for (int off = 16; off > 0; off >>= 1) {
        ps += __shfl_down_sync(0xffffffffu, ps, off);
        pd += __shfl_down_sync(0xffffffffu, pd, off);
    }
    const int lane = t & 31;
    const int half = (t >> 5) & 1;       // which warp within the head
    if (lane == 0) { red_src[hh][half] = ps; red_dst[hh][half] = pd; }
    __syncthreads();
    if (t < Hx) {
        g_esrc[(size_t)bid * Hx + t] = red_src[t][0] + red_src[t][1];
        g_edst[(size_t)bid * Hx + t] = red_dst[t][0] + red_dst[t][1];
    }
}

// ---------------------------------------------------------------------------
// Kernel 2: fused attention. Block = (b, tile of 16 m-rows). 256 threads.
// Loop over 64 j-tiles of 32: stage ht tile + adj + e_dst, compute exp
// weights into smem, then register-blocked accumulation (16 m x 4 j per
// inner step). Row-sum tracked per-thread, normalized at the end.
// ---------------------------------------------------------------------------
__global__ __launch_bounds__(256) void gat_attn_kernel(
    const float* __restrict__ adj,   // [N][N]
    float* __restrict__ out)         // [B][N][H*FOUT]
{
    __shared__ float ht_s[J_TILE][Hx * FOUT];     // 32 KB
    __shared__ float w_s[M_TILE][Hx][J_TILE];     // 8 KB, j contiguous
    __shared__ float adj_s[M_TILE][J_TILE];       // 2 KB
    __shared__ float edst_s[J_TILE][Hx];          // 512 B
    __shared__ float esrc_s[M_TILE][Hx];          // 256 B
    __shared__ float rsum_s[M_TILE][Hx];          // 256 B

    const int b  = blockIdx.y;
    const int m0 = blockIdx.x * M_TILE;
    const int t  = threadIdx.x;

    // weight-phase mapping: pair = (mm,h), 4 threads per pair each own 8 j's
    const int pair = t >> 2;        // 0..63
    const int jg   = t & 3;
    const int mm   = pair >> 2;     // 0..15
    const int hw   = pair & 3;      // 0..3
    // accumulate-phase mapping
    const int h2 = t >> 6;          // 0..3
    const int f  = t & 63;

    if (t < M_TILE * Hx) {
        int m = t >> 2, hh = t & 3;
        esrc_s[m][hh] = g_esrc[((size_t)b * Nx + m0 + m) * Hx + hh];
    }

    float acc[M_TILE];
#pragma unroll
    for (int m = 0; m < M_TILE; m++) acc[m] = 0.f;
    float rs_local = 0.f;

    __syncthreads();

    for (int jt = 0; jt < Nx / J_TILE; jt++) {
        const int j0 = jt * J_TILE;

        // --- stage tiles ---
#pragma unroll
        for (int k = 0; k < (J_TILE * Hx * FOUT) / 256; k++) {
            int idx = t + k * 256;
            int j = idx >> 8, c = idx & 255;
            ht_s[j][c] = g_ht[((size_t)b * Nx + j0 + j) * (Hx * FOUT) + c];
        }
        {
            int idx = t;                 // 512 adj entries, 2 per thread
            int m = idx >> 5, j = idx & 31;
            adj_s[m][j] = adj[(size_t)(m0 + m) * Nx + j0 + j];
            idx = t + 256; m = idx >> 5; j = idx & 31;
            adj_s[m][j] = adj[(size_t)(m0 + m) * Nx + j0 + j];
        }
        if (t < J_TILE * Hx) {
            int j = t >> 2, hh = t & 3;
            edst_s[j][hh] = g_edst[((size_t)b * Nx + j0 + j) * Hx + hh];
        }
        __syncthreads();

        // --- weights: w = adj * exp(leakyrelu(e_src + e_dst)) ---
        {
            const float es = esrc_s[mm][hw];
#pragma unroll
            for (int k = 0; k < 8; k++) {
                int j = jg * 8 + k;
                float ev = es + edst_s[j][hw];
                ev = (ev >= 0.f) ? ev : ALPHA * ev;
                float wv = adj_s[mm][j] * __expf(ev);
                w_s[mm][hw][j] = wv;
                rs_local += wv;
            }
        }
        __syncthreads();

        // --- accumulate: acc[m] += sum_j w[m][h2][j] * ht[j][h2*64+f] ---
        {
            const int c = h2 * FOUT + f;
            for (int j4 = 0; j4 < J_TILE; j4 += 4) {
                float hv0 = ht_s[j4 + 0][c];
                float hv1 = ht_s[j4 + 1][c];
                float hv2 = ht_s[j4 + 2][c];
                float hv3 = ht_s[j4 + 3][c];
#pragma unroll
                for (int m = 0; m < M_TILE; m++) {
                    float4 w4 = *reinterpret_cast<const float4*>(&w_s[m][h2][j4]);
                    acc[m] += w4.x * hv0;
                    acc[m] += w4.y * hv1;
                    acc[m] += w4.z * hv2;
                    acc[m] += w4.w * hv3;
                }
            }
        }
        __syncthreads();   // before next tile overwrites smem
    }

    // --- reduce row sums (4 threads per (mm,h) pair; consecutive lanes) ---
    rs_local += __shfl_down_sync(0xffffffffu, rs_local, 2);
    rs_local += __shfl_down_sync(0xffffffffu, rs_local, 1);
    if (jg == 0) rsum_s[mm][hw] = rs_local;
    __syncthreads();

    // --- normalize + store ---
#pragma unroll
    for (int m = 0; m < M_TILE; m++) {
        float inv = 1.f / rsum_s[m][h2];
        out[((size_t)b * Nx + m0 + m) * (Hx * FOUT) + h2 * FOUT + f] = acc[m] * inv;
    }
}

extern "C" void kernel_launch(void* const* d_in, const int* in_sizes, int n_in,
                              void* d_out, int out_size) {
    (void)in_sizes; (void)n_in; (void)out_size;
    const float* h   = (const float*)d_in[0];
    const float* adj = (const float*)d_in[1];
    const float* W   = (const float*)d_in[2];
    const float* a   = (const float*)d_in[3];
    float* out = (float*)d_out;

    gat_proj_kernel<<<Bx * Nx, 256>>>(h, W, a);
    dim3 grid(Nx / M_TILE, Bx);
    gat_attn_kernel<<<grid, 256>>>(adj, out);
}

// round 2
// speedup vs baseline: 1.6851x; 1.6851x over previous
#include <cuda_runtime.h>
#include <cuda_bf16.h>

// B=4, N=2048, F_in=128, F_out=64, H=4
#define Bx 4
#define Nx 2048
#define FIN 128
#define FOUT 64
#define Hx 4
#define ALPHA 0.2f

#define M_TILE 32
#define J_TILE 32
#define RPB 8           // rows per block in projection kernel

__device__ float g_ht[Bx * Nx * Hx * FOUT];     // 8 MB, [b][n][h*64+f]
__device__ float g_esrc[Bx * Nx * Hx];
__device__ float g_edst[Bx * Nx * Hx];

// ---------------------------------------------------------------------------
// Kernel 1: per block, 8 rows: ht = h @ W (4 heads) + e_src/e_dst dots.
// W column chunk held in registers, reused across the 8 rows.
// ---------------------------------------------------------------------------
__global__ __launch_bounds__(256) void gat_proj_kernel(
    const float* __restrict__ h,   // [B*N][FIN]
    const float* __restrict__ W,   // [H][FIN][FOUT]
    const float* __restrict__ a)   // [H][2*FOUT]
{
    __shared__ float h_s[RPB][FIN];
    __shared__ float red_s[RPB][Hx][2][2];   // [r][h][half][src|dst]

    const int base = blockIdx.x * RPB;       // row index into B*N
    const int t = threadIdx.x;
    const int hh = t >> 6, f = t & 63;
    const int lane = t & 31, half = (t >> 5) & 1;

    // stage 8 rows of h: 1024 floats = 256 float4
    ((float4*)h_s)[t] = ((const float4*)(h + (size_t)base * FIN))[t];
    const float asrc = a[hh * 2 * FOUT + f];
    const float adst = a[hh * 2 * FOUT + FOUT + f];
    __syncthreads();

    const float* Wp = W + hh * FIN * FOUT + f;
    float acc[RPB];
#pragma unroll
    for (int r = 0; r < RPB; r++) acc[r] = 0.f;

    for (int i0 = 0; i0 < FIN; i0 += 16) {
        float wreg[16];
#pragma unroll
        for (int i = 0; i < 16; i++) wreg[i] = Wp[(i0 + i) * FOUT];
#pragma unroll
        for (int r = 0; r < RPB; r++) {
#pragma unroll
            for (int iq = 0; iq < 4; iq++) {
                float4 hv = *(const float4*)&h_s[r][i0 + iq * 4];
                acc[r] = fmaf(hv.x, wreg[iq * 4 + 0], acc[r]);
                acc[r] = fmaf(hv.y, wreg[iq * 4 + 1], acc[r]);
                acc[r] = fmaf(hv.z, wreg[iq * 4 + 2], acc[r]);
                acc[r] = fmaf(hv.w, wreg[iq * 4 + 3], acc[r]);
            }
        }
    }

#pragma unroll
    for (int r = 0; r < RPB; r++) {
        g_ht[(size_t)(base + r) * (Hx * FOUT) + t] = acc[r];
        float ps = acc[r] * asrc, pd = acc[r] * adst;
#pragma unroll
        for (int off = 16; off > 0; off >>= 1) {
            ps += __shfl_down_sync(0xffffffffu, ps, off);
            pd += __shfl_down_sync(0xffffffffu, pd, off);
        }
        if (lane == 0) { red_s[r][hh][half][0] = ps; red_s[r][hh][half][1] = pd; }
    }
    __syncthreads();
    if (t < RPB * Hx) {
        int r = t >> 2, h2 = t & 3;
        g_esrc[(size_t)(base + r) * Hx + h2] = red_s[r][h2][0][0] + red_s[r][h2][1][0];
        g_edst[(size_t)(base + r) * Hx + h2] = red_s[r][h2][0][1] + red_s[r][h2][1][1];
    }
}

// ---------------------------------------------------------------------------
// Kernel 2: fused attention. Block = (b, 32 m-rows), 256 threads.
// Weight phase: lane = j (conflict-free stores, coalesced adj).
// Accumulate phase: thread owns 8 m x 4 f -> one w4 LDS feeds 16 FFMAs.
// Row sums carried in registers, reduced once at the end.
// ---------------------------------------------------------------------------
__global__ __launch_bounds__(256, 2) void gat_attn_kernel(
    const float* __restrict__ adj,   // [N][N]
    float* __restrict__ out)         // [B][N][H*FOUT]
{
    __shared__ float ht_s[J_TILE][Hx * FOUT];     // 32 KB
    __shared__ float w_s[M_TILE][Hx][J_TILE];     // 16 KB  (total = 48 KB)

    const int b  = blockIdx.y;
    const int m0 = blockIdx.x * M_TILE;
    const int t  = threadIdx.x;
    const int lane = t & 31, warpid = t >> 5;
    // accumulate mapping
    const int h2 = t >> 6;
    const int mg = (t >> 4) & 3;
    const int f4 = t & 15;
    const int c  = h2 * FOUT + f4 * 4;

    // e_src for this warp's 4 m-rows x 4 heads, in registers
    float esrc_r[16];
#pragma unroll
    for (int mm = 0; mm < 4; mm++)
#pragma unroll
        for (int hh = 0; hh < 4; hh++)
            esrc_r[mm * 4 + hh] =
                g_esrc[(size_t)(b * Nx + m0 + warpid * 4 + mm) * Hx + hh];

    float rs[16];
#pragma unroll
    for (int k = 0; k < 16; k++) rs[k] = 0.f;

    float4 acc[8];
#pragma unroll
    for (int k = 0; k < 8; k++) acc[k] = make_float4(0.f, 0.f, 0.f, 0.f);

    for (int jt = 0; jt < Nx / J_TILE; jt++) {
        const int j0 = jt * J_TILE;

        // --- stage ht tile: 2048 float4, 8 per thread ---
#pragma unroll
        for (int k = 0; k < 8; k++) {
            int idx = t + k * 256;
            int j = idx >> 6, cc = idx & 63;
            ((float4*)ht_s[j])[cc] =
                ((const float4*)(g_ht + (size_t)(b * Nx + j0 + j) * (Hx * FOUT)))[cc];
        }

        // --- weights: w = adj * exp(leakyrelu(e_src + e_dst)), lane = j ---
        {
            float4 ed4 = *(const float4*)(g_edst + (size_t)(b * Nx + j0 + lane) * Hx);
#pragma unroll
            for (int mm = 0; mm < 4; mm++) {
                int m = warpid * 4 + mm;
                float av = adj[(size_t)(m0 + m) * Nx + j0 + lane];
#pragma unroll
                for (int hh = 0; hh < 4; hh++) {
                    float ed = (hh == 0) ? ed4.x : (hh == 1) ? ed4.y
                             : (hh == 2) ? ed4.z : ed4.w;
                    float ev = esrc_r[mm * 4 + hh] + ed;
                    ev = (ev >= 0.f) ? ev : ALPHA * ev;
                    float wv = av * __expf(ev);
                    w_s[m][hh][lane] = wv;
                    rs[mm * 4 + hh] += wv;
                }
            }
        }
        __syncthreads();

        // --- accumulate: acc[k][0..3] += w[m][h2][j] * ht[j][c..c+3] ---
#pragma unroll
        for (int j4 = 0; j4 < J_TILE; j4 += 4) {
            float4 hv0 = *(const float4*)&ht_s[j4 + 0][c];
            float4 hv1 = *(const float4*)&ht_s[j4 + 1][c];
            float4 hv2 = *(const float4*)&ht_s[j4 + 2][c];
            float4 hv3 = *(const float4*)&ht_s[j4 + 3][c];
#pragma unroll
            for (int k = 0; k < 8; k++) {
                float4 w4 = *(const float4*)&w_s[mg * 8 + k][h2][j4];
                acc[k].x = fmaf(w4.x, hv0.x, acc[k].x);
                acc[k].y = fmaf(w4.x, hv0.y, acc[k].y);
                acc[k].z = fmaf(w4.x, hv0.z, acc[k].z);
                acc[k].w = fmaf(w4.x, hv0.w, acc[k].w);
                acc[k].x = fmaf(w4.y, hv1.x, acc[k].x);
                acc[k].y = fmaf(w4.y, hv1.y, acc[k].y);
                acc[k].z = fmaf(w4.y, hv1.z, acc[k].z);
                acc[k].w = fmaf(w4.y, hv1.w, acc[k].w);
                acc[k].x = fmaf(w4.z, hv2.x, acc[k].x);
                acc[k].y = fmaf(w4.z, hv2.y, acc[k].y);
                acc[k].z = fmaf(w4.z, hv2.z, acc[k].z);
                acc[k].w = fmaf(w4.z, hv2.w, acc[k].w);
                acc[k].x = fmaf(w4.w, hv3.x, acc[k].x);
                acc[k].y = fmaf(w4.w, hv3.y, acc[k].y);
                acc[k].z = fmaf(w4.w, hv3.z, acc[k].z);
                acc[k].w = fmaf(w4.w, hv3.w, acc[k].w);
            }
        }
        __syncthreads();
    }

    // --- row-sum butterfly reduction (all 16 pairs per warp) ---
#pragma unroll
    for (int k = 0; k < 16; k++) {
#pragma unroll
        for (int off = 16; off > 0; off >>= 1)
            rs[k] += __shfl_xor_sync(0xffffffffu, rs[k], off);
    }
    float* rsum_s = (float*)ht_s;   // reuse (safe: after last accumulate sync)
    if (lane == 0) {
#pragma unroll
        for (int k = 0; k < 16; k++)
            rsum_s[(warpid * 4 + (k >> 2)) * Hx + (k & 3)] = rs[k];
    }
    __syncthreads();

    // --- normalize + store ---
#pragma unroll
    for (int k = 0; k < 8; k++) {
        int m = mg * 8 + k;
        float inv = 1.f / rsum_s[m * Hx + h2];
        float4 o;
        o.x = acc[k].x * inv; o.y = acc[k].y * inv;
        o.z = acc[k].z * inv; o.w = acc[k].w * inv;
        *(float4*)(out + (size_t)(b * Nx + m0 + m) * (Hx * FOUT) + c) = o;
    }
}

extern "C" void kernel_launch(void* const* d_in, const int* in_sizes, int n_in,
                              void* d_out, int out_size) {
    (void)in_sizes; (void)n_in; (void)out_size;
    const float* h   = (const float*)d_in[0];
    const float* adj = (const float*)d_in[1];
    const float* W   = (const float*)d_in[2];
    const float* a   = (const float*)d_in[3];
    float* out = (float*)d_out;

    gat_proj_kernel<<<(Bx * Nx) / RPB, 256>>>(h, W, a);
    dim3 grid(Nx / M_TILE, Bx);
    gat_attn_kernel<<<grid, 256>>>(adj, out);
}

// round 4
// speedup vs baseline: 2.3257x; 1.3801x over previous
#include <cuda_runtime.h>
#include <cstdint>

// B=4, N=2048, F_in=128, F_out=64, H=4
#define Bx 4
#define Nx 2048
#define FIN 128
#define FOUT 64
#define Hx 4
#define ALPHA 0.2f
#define RPB 8

#define MT 128
#define JT 128
#define NTILES (Nx / JT)

// Scratch
__device__ float g_htT[(size_t)Bx * Hx * FOUT * Nx];   // [b][h][f][n], tf32-rounded
__device__ float g_esrcT[Bx * Hx * Nx];                // [b][h][n]
__device__ float g_edstT[Bx * Hx * Nx];                // [b][h][n]

__device__ __forceinline__ uint32_t tf32b(float x) {
    uint32_t r;
    asm("cvt.rna.tf32.f32 %0, %1;" : "=r"(r) : "f"(x));
    return r;
}

// smem layout (floats). Row stride 132 makes fragment loads conflict-free.
#define WS_OFF 0                         // w tile: 128 x 132
#define HS_OFF (128 * 132)               // htT tile: 64 x 132
#define RS_OFF (HS_OFF + 64 * 132)       // row sums: 128
#define SM_FLOATS (RS_OFF + 128)
#define SM_TOTAL (SM_FLOATS * 4)         // 101888 B

// ---------------------------------------------------------------------------
// Kernel 1: projection -> g_htT (tf32, transposed), e_src/e_dst (fp32)
// ---------------------------------------------------------------------------
__global__ __launch_bounds__(256) void gat_proj_kernel(
    const float* __restrict__ h, const float* __restrict__ W, const float* __restrict__ a)
{
    __shared__ float h_s[RPB][FIN];
    __shared__ float red_s[RPB][Hx][2][2];

    const int base = blockIdx.x * RPB;
    const int b = base >> 11, n0 = base & (Nx - 1);
    const int t = threadIdx.x;
    const int hh = t >> 6, f = t & 63;
    const int lane = t & 31, half = (t >> 5) & 1;

    ((float4*)h_s)[t] = ((const float4*)(h + (size_t)base * FIN))[t];
    const float asrc = a[hh * 2 * FOUT + f];
    const float adst = a[hh * 2 * FOUT + FOUT + f];
    __syncthreads();

    const float* Wp = W + hh * FIN * FOUT + f;
    float acc[RPB];
#pragma unroll
    for (int r = 0; r < RPB; r++) acc[r] = 0.f;

    for (int i0 = 0; i0 < FIN; i0 += 16) {
        float wreg[16];
#pragma unroll
        for (int i = 0; i < 16; i++) wreg[i] = Wp[(i0 + i) * FOUT];
#pragma unroll
        for (int r = 0; r < RPB; r++) {
#pragma unroll
            for (int iq = 0; iq < 4; iq++) {
                float4 hv = *(const float4*)&h_s[r][i0 + iq * 4];
                acc[r] = fmaf(hv.x, wreg[iq * 4 + 0], acc[r]);
                acc[r] = fmaf(hv.y, wreg[iq * 4 + 1], acc[r]);
                acc[r] = fmaf(hv.z, wreg[iq * 4 + 2], acc[r]);
                acc[r] = fmaf(hv.w, wreg[iq * 4 + 3], acc[r]);
            }
        }
    }

    {
        float* dst = g_htT + ((size_t)(b * Hx + hh) * FOUT + f) * Nx + n0;
        float4 v0, v1;
        v0.x = __uint_as_float(tf32b(acc[0])); v0.y = __uint_as_float(tf32b(acc[1]));
        v0.z = __uint_as_float(tf32b(acc[2])); v0.w = __uint_as_float(tf32b(acc[3]));
        v1.x = __uint_as_float(tf32b(acc[4])); v1.y = __uint_as_float(tf32b(acc[5]));
        v1.z = __uint_as_float(tf32b(acc[6])); v1.w = __uint_as_float(tf32b(acc[7]));
        *(float4*)dst = v0;
        *(float4*)(dst + 4) = v1;
    }

#pragma unroll
    for (int r = 0; r < RPB; r++) {
        float ps = acc[r] * asrc, pd = acc[r] * adst;
#pragma unroll
        for (int off = 16; off > 0; off >>= 1) {
            ps += __shfl_down_sync(0xffffffffu, ps, off);
            pd += __shfl_down_sync(0xffffffffu, pd, off);
        }
        if (lane == 0) { red_s[r][hh][half][0] = ps; red_s[r][hh][half][1] = pd; }
    }
    __syncthreads();
    if (t < RPB * Hx) {
        int r = t >> 2, h2 = t & 3;
        g_esrcT[(b * Hx + h2) * Nx + n0 + r] = red_s[r][h2][0][0] + red_s[r][h2][1][0];
        g_edstT[(b * Hx + h2) * Nx + n0 + r] = red_s[r][h2][0][1] + red_s[r][h2][1][1];
    }
}

// ---------------------------------------------------------------------------
// Kernel 2: flash attention with mma.sync tf32 (m16n8k8).
// Block = 256 threads, (m-tile 128, h, b). 8 warps: warp = (khalf, mgroup),
// warp tile = 32 m x 64 f over half the k (64 j) of each 128-j tile.
// ---------------------------------------------------------------------------
__global__ __launch_bounds__(256, 2) void gat_attn_mma(
    const float* __restrict__ adj, float* __restrict__ out)
{
    extern __shared__ float sm[];
    float* w_s  = sm + WS_OFF;
    float* hs   = sm + HS_OFF;
    float* rsum = sm + RS_OFF;

    const int t = threadIdx.x, lane = t & 31, wid = t >> 5;
    const int b = blockIdx.z, hh = blockIdx.y, m0 = blockIdx.x * MT;
    const int mg = wid & 3, khalf = wid >> 2;
    const int gq = lane >> 2, tq = lane & 3;   // mma groupID / threadID-in-group

    // producer mapping: thread -> (m row, half of j)
    const int pm = t >> 1;
    const int jh = (t & 1) * 64;
    const float es = g_esrcT[(b * Hx + hh) * Nx + m0 + pm];
    float rs = 0.f;
    const float* edp0  = g_edstT + (size_t)(b * Hx + hh) * Nx + jh;
    const float* adjp0 = adj + (size_t)(m0 + pm) * Nx + jh;
    // htT loader mapping
    const int bf = t >> 2, bj = (t & 3) * 32;
    const float* bsrc0 = g_htT + ((size_t)(b * Hx + hh) * FOUT + bf) * Nx + bj;

    float acc[2][8][4];
#pragma unroll
    for (int s = 0; s < 2; s++)
#pragma unroll
        for (int nt = 0; nt < 8; nt++)
#pragma unroll
            for (int i = 0; i < 4; i++) acc[s][nt][i] = 0.f;

    for (int jt = 0; jt < NTILES; jt++) {
        const int j0 = jt * JT;

        // ---- stage htT tile [64 f][128 j] ----
        {
            const float4* src = (const float4*)(bsrc0 + j0);
#pragma unroll
            for (int k = 0; k < 8; k++)
                *(float4*)&hs[bf * 132 + bj + 4 * k] = src[k];
        }
        // ---- produce w tile: w = adj * exp(lrelu(e_src+e_dst)), tf32 ----
        {
            const float4* ap = (const float4*)(adjp0 + j0);
            const float4* ep = (const float4*)(edp0 + j0);
#pragma unroll 4
            for (int q = 0; q < 16; q++) {
                float4 av = ap[q];
                float4 ed = ep[q];
                float e0 = es + ed.x; e0 = fmaxf(e0, ALPHA * e0);
                float e1 = es + ed.y; e1 = fmaxf(e1, ALPHA * e1);
                float e2 = es + ed.z; e2 = fmaxf(e2, ALPHA * e2);
                float e3 = es + ed.w; e3 = fmaxf(e3, ALPHA * e3);
                float w0 = av.x * __expf(e0);
                float w1 = av.y * __expf(e1);
                float w2 = av.z * __expf(e2);
                float w3 = av.w * __expf(e3);
                rs += (w0 + w1) + (w2 + w3);
                float4 wv;
                wv.x = __uint_as_float(tf32b(w0));
                wv.y = __uint_as_float(tf32b(w1));
                wv.z = __uint_as_float(tf32b(w2));
                wv.w = __uint_as_float(tf32b(w3));
                *(float4*)&w_s[pm * 132 + jh + q * 4] = wv;
            }
        }
        __syncthreads();

        // ---- consume: mma over this warp's k half (8 chunks of k8) ----
#pragma unroll 2
        for (int ch = 0; ch < 8; ch++) {
            const int kb = khalf * 64 + ch * 8;
            uint32_t afr[2][4];
#pragma unroll
            for (int s = 0; s < 2; s++) {
                const int r0 = (mg * 32 + s * 16 + gq) * 132 + kb + tq;
                afr[s][0] = __float_as_uint(w_s[r0]);
                afr[s][1] = __float_as_uint(w_s[r0 + 8 * 132]);
                afr[s][2] = __float_as_uint(w_s[r0 + 4]);
                afr[s][3] = __float_as_uint(w_s[r0 + 8 * 132 + 4]);
            }
#pragma unroll
            for (int nt = 0; nt < 8; nt++) {
                const int fb = (nt * 8 + gq) * 132 + kb + tq;
                uint32_t b0 = __float_as_uint(hs[fb]);
                uint32_t b1 = __float_as_uint(hs[fb + 4]);
#pragma unroll
                for (int s = 0; s < 2; s++) {
                    asm volatile(
                        "mma.sync.aligned.m16n8k8.row.col.f32.tf32.tf32.f32 "
                        "{%0,%1,%2,%3},{%4,%5,%6,%7},{%8,%9},{%0,%1,%2,%3};"
                        : "+f"(acc[s][nt][0]), "+f"(acc[s][nt][1]),
                          "+f"(acc[s][nt][2]), "+f"(acc[s][nt][3])
                        : "r"(afr[s][0]), "r"(afr[s][1]), "r"(afr[s][2]), "r"(afr[s][3]),
                          "r"(b0), "r"(b1));
                }
            }
        }
        __syncthreads();
    }

    // ---- row sums ----
    rs += __shfl_xor_sync(0xffffffffu, rs, 1);
    if (!(t & 1)) rsum[pm] = rs;

    // ---- k-split reduction: khalf=1 warps park partials in smem (reuse w_s) ----
    float* red = sm;   // 4*32*65 = 8320 floats, fits in w_s region
    if (khalf == 1) {
#pragma unroll
        for (int s = 0; s < 2; s++)
#pragma unroll
            for (int nt = 0; nt < 8; nt++)
#pragma unroll
                for (int i = 0; i < 4; i++)
                    red[(mg * 32 + lane) * 65 + s * 32 + nt * 4 + i] = acc[s][nt][i];
    }
    __syncthreads();

    // ---- khalf=0 warps: combine, normalize, store ----
    if (khalf == 0) {
        const float* rp = &red[(mg * 32 + lane) * 65];
#pragma unroll
        for (int s = 0; s < 2; s++) {
            const int mrow = mg * 32 + s * 16 + gq;
            const float inv0 = 1.f / rsum[mrow];
            const float inv1 = 1.f / rsum[mrow + 8];
            float* op0 = out + (size_t)(b * Nx + m0 + mrow) * (Hx * FOUT) + hh * FOUT;
            float* op1 = op0 + (size_t)8 * (Hx * FOUT);
#pragma unroll
            for (int nt = 0; nt < 8; nt++) {
                float2 v0, v1;
                v0.x = (acc[s][nt][0] + rp[s * 32 + nt * 4 + 0]) * inv0;
                v0.y = (acc[s][nt][1] + rp[s * 32 + nt * 4 + 1]) * inv0;
                v1.x = (acc[s][nt][2] + rp[s * 32 + nt * 4 + 2]) * inv1;
                v1.y = (acc[s][nt][3] + rp[s * 32 + nt * 4 + 3]) * inv1;
                const int col = nt * 8 + 2 * tq;
                *(float2*)(op0 + col) = v0;
                *(float2*)(op1 + col) = v1;
            }
        }
    }
}

extern "C" void kernel_launch(void* const* d_in, const int* in_sizes, int n_in,
                              void* d_out, int out_size) {
    (void)in_sizes; (void)n_in; (void)out_size;
    const float* h   = (const float*)d_in[0];
    const float* adj = (const float*)d_in[1];
    const float* W   = (const float*)d_in[2];
    const float* a   = (const float*)d_in[3];
    float* out = (float*)d_out;

    cudaFuncSetAttribute(gat_attn_mma, cudaFuncAttributeMaxDynamicSharedMemorySize, SM_TOTAL);

    gat_proj_kernel<<<(Bx * Nx) / RPB, 256>>>(h, W, a);
    dim3 grid(Nx / MT, Hx, Bx);
    gat_attn_mma<<<grid, 256, SM_TOTAL>>>(adj, out);
}

// round 5
// speedup vs baseline: 3.2755x; 1.4084x over previous
#include <cuda_runtime.h>
#include <cstdint>

// B=4, N=2048, F_in=128, F_out=64, H=4
#define Bx 4
#define Nx 2048
#define FIN 128
#define FOUT 64
#define Hx 4
#define ALPHA 0.2f
#define RPB 8

#define MT 128
#define JT 128
#define NTILES (Nx / JT)
#define TSTRIDE 132                       // floats per row in tiles
#define TILE_FLOATS (64 * TSTRIDE)        // 8448 per (b,h,jt) htT tile

// Scratch: htT in smem-tile layout [b][h][jt][64 f][132]
__device__ float g_htT[(size_t)Bx * Hx * NTILES * TILE_FLOATS];
__device__ float g_esrcT[Bx * Hx * Nx];
__device__ float g_edstT[Bx * Hx * Nx];

__device__ __forceinline__ uint32_t tf32b(float x) {
    uint32_t r;
    asm("cvt.rna.tf32.f32 %0, %1;" : "=r"(r) : "f"(x));
    return r;
}

// smem: w tile 128x132, hs tile 64x132, rsum 128x2
#define WS_OFF 0
#define HS_OFF (128 * TSTRIDE)
#define RS_OFF (HS_OFF + 64 * TSTRIDE)
#define SM_FLOATS (RS_OFF + 256)
#define SM_TOTAL (SM_FLOATS * 4)          // 102,400 B

// ---------------------------------------------------------------------------
// Kernel 1: projection -> g_htT (tf32, tiled layout), e_src/e_dst (fp32)
// ---------------------------------------------------------------------------
__global__ __launch_bounds__(256) void gat_proj_kernel(
    const float* __restrict__ h, const float* __restrict__ W, const float* __restrict__ a)
{
    __shared__ float h_s[RPB][FIN];
    __shared__ float red_s[RPB][Hx][2][2];

    const int base = blockIdx.x * RPB;
    const int b = base >> 11, n0 = base & (Nx - 1);
    const int t = threadIdx.x;
    const int hh = t >> 6, f = t & 63;
    const int lane = t & 31, half = (t >> 5) & 1;

    ((float4*)h_s)[t] = ((const float4*)(h + (size_t)base * FIN))[t];
    const float asrc = a[hh * 2 * FOUT + f];
    const float adst = a[hh * 2 * FOUT + FOUT + f];
    __syncthreads();

    const float* Wp = W + hh * FIN * FOUT + f;
    float acc[RPB];
#pragma unroll
    for (int r = 0; r < RPB; r++) acc[r] = 0.f;

    for (int i0 = 0; i0 < FIN; i0 += 16) {
        float wreg[16];
#pragma unroll
        for (int i = 0; i < 16; i++) wreg[i] = Wp[(i0 + i) * FOUT];
#pragma unroll
        for (int r = 0; r < RPB; r++) {
#pragma unroll
            for (int iq = 0; iq < 4; iq++) {
                float4 hv = *(const float4*)&h_s[r][i0 + iq * 4];
                acc[r] = fmaf(hv.x, wreg[iq * 4 + 0], acc[r]);
                acc[r] = fmaf(hv.y, wreg[iq * 4 + 1], acc[r]);
                acc[r] = fmaf(hv.z, wreg[iq * 4 + 2], acc[r]);
                acc[r] = fmaf(hv.w, wreg[iq * 4 + 3], acc[r]);
            }
        }
    }

    // store into tiled layout: tile jt = n>>7, col = n&127
    {
        const int jt = n0 >> 7, jc = n0 & 127;
        float* dst = g_htT + (((size_t)(b * Hx + hh) * NTILES + jt) * 64 + f) * TSTRIDE + jc;
        float4 v0, v1;
        v0.x = __uint_as_float(tf32b(acc[0])); v0.y = __uint_as_float(tf32b(acc[1]));
        v0.z = __uint_as_float(tf32b(acc[2])); v0.w = __uint_as_float(tf32b(acc[3]));
        v1.x = __uint_as_float(tf32b(acc[4])); v1.y = __uint_as_float(tf32b(acc[5]));
        v1.z = __uint_as_float(tf32b(acc[6])); v1.w = __uint_as_float(tf32b(acc[7]));
        *(float4*)dst = v0;
        *(float4*)(dst + 4) = v1;
    }

#pragma unroll
    for (int r = 0; r < RPB; r++) {
        float ps = acc[r] * asrc, pd = acc[r] * adst;
#pragma unroll
        for (int off = 16; off > 0; off >>= 1) {
            ps += __shfl_down_sync(0xffffffffu, ps, off);
            pd += __shfl_down_sync(0xffffffffu, pd, off);
        }
        if (lane == 0) { red_s[r][hh][half][0] = ps; red_s[r][hh][half][1] = pd; }
    }
    __syncthreads();
    if (t < RPB * Hx) {
        int r = t >> 2, h2 = t & 3;
        g_esrcT[(b * Hx + h2) * Nx + n0 + r] = red_s[r][h2][0][0] + red_s[r][h2][1][0];
        g_edstT[(b * Hx + h2) * Nx + n0 + r] = red_s[r][h2][0][1] + red_s[r][h2][1][1];
    }
}

// ---------------------------------------------------------------------------
// Kernel 2: flash attention, mma.sync tf32. Block = (m128, h, b), 256 thr.
// Conflict-free staging; 8 warps = 4 mgroups x 2 khalves.
// ---------------------------------------------------------------------------
__global__ __launch_bounds__(256, 2) void gat_attn_mma(
    const float* __restrict__ adj, float* __restrict__ out)
{
    extern __shared__ float sm[];
    float* w_s   = sm + WS_OFF;
    float* hs    = sm + HS_OFF;
    float* rsum2 = sm + RS_OFF;

    const int t = threadIdx.x, lane = t & 31, wid = t >> 5;
    const int b = blockIdx.z, hh = blockIdx.y, m0 = blockIdx.x * MT;
    const int mg = wid & 3, khalf = wid >> 2;
    const int gq = lane >> 2, tq = lane & 3;

    // producer mapping: row pm = t&127, j-half = t>>7 (conflict-free STS)
    const int pm = t & 127;
    const int jhalf = t >> 7;           // 0 or 1
    const int jh = jhalf * 64;
    const float es = g_esrcT[(b * Hx + hh) * Nx + m0 + pm];
    float rs = 0.f;
    const float* edp0  = g_edstT + (size_t)(b * Hx + hh) * Nx + jh;
    const float* adjp0 = adj + (size_t)(m0 + pm) * Nx + jh;
    const float* hsrc0 = g_htT + (size_t)(b * Hx + hh) * NTILES * TILE_FLOATS;

    float acc[2][8][4];
#pragma unroll
    for (int s = 0; s < 2; s++)
#pragma unroll
        for (int nt = 0; nt < 8; nt++)
#pragma unroll
            for (int i = 0; i < 4; i++) acc[s][nt][i] = 0.f;

    for (int jt = 0; jt < NTILES; jt++) {
        const int j0 = jt * JT;

        // ---- stage htT tile: linear copy, coalesced + conflict-free ----
        {
            const float4* src = (const float4*)(hsrc0 + (size_t)jt * TILE_FLOATS);
            float4* dst = (float4*)hs;
#pragma unroll
            for (int k = 0; k < 8; k++) dst[t + 256 * k] = src[t + 256 * k];
            if (t < TILE_FLOATS / 4 - 2048) dst[t + 2048] = src[t + 2048];
        }
        // ---- produce w tile (conflict-free STS) ----
        {
            const float4* ap = (const float4*)(adjp0 + j0);
            const float4* ep = (const float4*)(edp0 + j0);
#pragma unroll 4
            for (int q = 0; q < 16; q++) {
                float4 av = ap[q];
                float4 ed = ep[q];          // warp-broadcast (same addr per warp)
                float e0 = es + ed.x; e0 = fmaxf(e0, ALPHA * e0);
                float e1 = es + ed.y; e1 = fmaxf(e1, ALPHA * e1);
                float e2 = es + ed.z; e2 = fmaxf(e2, ALPHA * e2);
                float e3 = es + ed.w; e3 = fmaxf(e3, ALPHA * e3);
                float w0 = av.x * __expf(e0);
                float w1 = av.y * __expf(e1);
                float w2 = av.z * __expf(e2);
                float w3 = av.w * __expf(e3);
                rs += (w0 + w1) + (w2 + w3);
                float4 wv;
                wv.x = __uint_as_float(tf32b(w0));
                wv.y = __uint_as_float(tf32b(w1));
                wv.z = __uint_as_float(tf32b(w2));
                wv.w = __uint_as_float(tf32b(w3));
                *(float4*)&w_s[pm * TSTRIDE + jh + q * 4] = wv;
            }
        }
        __syncthreads();

        // ---- consume: mma over warp's k half ----
#pragma unroll 2
        for (int ch = 0; ch < 8; ch++) {
            const int kb = khalf * 64 + ch * 8;
            uint32_t afr[2][4];
#pragma unroll
            for (int s = 0; s < 2; s++) {
                const int r0 = (mg * 32 + s * 16 + gq) * TSTRIDE + kb + tq;
                afr[s][0] = __float_as_uint(w_s[r0]);
                afr[s][1] = __float_as_uint(w_s[r0 + 8 * TSTRIDE]);
                afr[s][2] = __float_as_uint(w_s[r0 + 4]);
                afr[s][3] = __float_as_uint(w_s[r0 + 8 * TSTRIDE + 4]);
            }
#pragma unroll
            for (int nt = 0; nt < 8; nt++) {
                const int fb = (nt * 8 + gq) * TSTRIDE + kb + tq;
                uint32_t b0 = __float_as_uint(hs[fb]);
                uint32_t b1 = __float_as_uint(hs[fb + 4]);
#pragma unroll
                for (int s = 0; s < 2; s++) {
                    asm volatile(
                        "mma.sync.aligned.m16n8k8.row.col.f32.tf32.tf32.f32 "
                        "{%0,%1,%2,%3},{%4,%5,%6,%7},{%8,%9},{%0,%1,%2,%3};"
                        : "+f"(acc[s][nt][0]), "+f"(acc[s][nt][1]),
                          "+f"(acc[s][nt][2]), "+f"(acc[s][nt][3])
                        : "r"(afr[s][0]), "r"(afr[s][1]), "r"(afr[s][2]), "r"(afr[s][3]),
                          "r"(b0), "r"(b1));
                }
            }
        }
        __syncthreads();
    }

    // ---- row sums: two halves per row ----
    rsum2[pm * 2 + jhalf] = rs;

    // ---- k-split partials to smem (reuse w_s region) ----
    float* red = sm;
    if (khalf == 1) {
#pragma unroll
        for (int s = 0; s < 2; s++)
#pragma unroll
            for (int nt = 0; nt < 8; nt++)
#pragma unroll
                for (int i = 0; i < 4; i++)
                    red[(mg * 32 + lane) * 65 + s * 32 + nt * 4 + i] = acc[s][nt][i];
    }
    __syncthreads();

    if (khalf == 0) {
        const float* rp = &red[(mg * 32 + lane) * 65];
#pragma unroll
        for (int s = 0; s < 2; s++) {
            const int mrow = mg * 32 + s * 16 + gq;
            const float inv0 = 1.f / (rsum2[mrow * 2] + rsum2[mrow * 2 + 1]);
            const float inv1 = 1.f / (rsum2[(mrow + 8) * 2] + rsum2[(mrow + 8) * 2 + 1]);
            float* op0 = out + (size_t)(b * Nx + m0 + mrow) * (Hx * FOUT) + hh * FOUT;
            float* op1 = op0 + (size_t)8 * (Hx * FOUT);
#pragma unroll
            for (int nt = 0; nt < 8; nt++) {
                float2 v0, v1;
                v0.x = (acc[s][nt][0] + rp[s * 32 + nt * 4 + 0]) * inv0;
                v0.y = (acc[s][nt][1] + rp[s * 32 + nt * 4 + 1]) * inv0;
                v1.x = (acc[s][nt][2] + rp[s * 32 + nt * 4 + 2]) * inv1;
                v1.y = (acc[s][nt][3] + rp[s * 32 + nt * 4 + 3]) * inv1;
                const int col = nt * 8 + 2 * tq;
                *(float2*)(op0 + col) = v0;
                *(float2*)(op1 + col) = v1;
            }
        }
    }
}

extern "C" void kernel_launch(void* const* d_in, const int* in_sizes, int n_in,
                              void* d_out, int out_size) {
    (void)in_sizes; (void)n_in; (void)out_size;
    const float* h   = (const float*)d_in[0];
    const float* adj = (const float*)d_in[1];
    const float* W   = (const float*)d_in[2];
    const float* a   = (const float*)d_in[3];
    float* out = (float*)d_out;

    cudaFuncSetAttribute(gat_attn_mma, cudaFuncAttributeMaxDynamicSharedMemorySize, SM_TOTAL);

    gat_proj_kernel<<<(Bx * Nx) / RPB, 256>>>(h, W, a);
    dim3 grid(Nx / MT, Hx, Bx);
    gat_attn_mma<<<grid, 256, SM_TOTAL>>>(adj, out);
}

// round 6
// speedup vs baseline: 5.6608x; 1.7282x over previous
#include <cuda_runtime.h>
#include <cuda_fp16.h>
#include <cstdint>

// B=4, N=2048, F_in=128, F_out=64, H=4
#define Bx 4
#define Nx 2048
#define FIN 128
#define FOUT 64
#define Hx 4
#define ALPHA 0.2f
#define RPB 8

#define MT 128
#define JT 128
#define NTILES (Nx / JT)
#define TSH 136                 // halves per smem tile row
#define TSH32 (TSH / 2)         // 68 b32 per row
#define HT_TILE_H (64 * 128)    // halves per (b,h,jt) htT tile (dense)

// Scratch
__device__ __half g_htT[(size_t)Bx * Hx * NTILES * HT_TILE_H];   // 4 MB
__device__ float g_esrcT[Bx * Hx * Nx];
__device__ float g_edstT[Bx * Hx * Nx];
__device__ uint32_t g_adjbits[Nx * (Nx / 32)];                   // 512 KB
__device__ float g_maxd[Bx * Hx];

// smem: w tile 128x136 half (34816B), hs 64x136 half (17408B), rsum 256 f32
#define WS_BYTES (128 * TSH * 2)
#define HS_BYTES (64 * TSH * 2)
#define RS_OFF (WS_BYTES + HS_BYTES)
#define SM_TOTAL (RS_OFF + 256 * 4)      // 53248 B

// ---------------------------------------------------------------------------
// Kernel 0: pack adj into bitmask. 512 blocks x 256. Warp handles 1024 cols.
// ---------------------------------------------------------------------------
__global__ __launch_bounds__(256) void adj_bits_kernel(const float* __restrict__ adj)
{
    const int gw = (blockIdx.x * 256 + threadIdx.x) >> 5;   // global warp 0..4095
    const int lane = threadIdx.x & 31;
    const size_t base = (size_t)gw * 1024;
#pragma unroll 4
    for (int it = 0; it < 32; it++) {
        float v = adj[base + it * 32 + lane];
        uint32_t m = __ballot_sync(0xffffffffu, v > 0.5f);
        if (lane == 0) g_adjbits[gw * 32 + it] = m;
    }
}

// ---------------------------------------------------------------------------
// Kernel 1: projection -> g_htT (fp16, tiled [64 f][128 j]), e_src/e_dst fp32
// ---------------------------------------------------------------------------
__global__ __launch_bounds__(256) void gat_proj_kernel(
    const float* __restrict__ h, const float* __restrict__ W, const float* __restrict__ a)
{
    __shared__ float h_s[RPB][FIN];
    __shared__ float red_s[RPB][Hx][2][2];

    const int base = blockIdx.x * RPB;
    const int b = base >> 11, n0 = base & (Nx - 1);
    const int t = threadIdx.x;
    const int hh = t >> 6, f = t & 63;
    const int lane = t & 31, half = (t >> 5) & 1;

    ((float4*)h_s)[t] = ((const float4*)(h + (size_t)base * FIN))[t];
    const float asrc = a[hh * 2 * FOUT + f];
    const float adst = a[hh * 2 * FOUT + FOUT + f];
    __syncthreads();

    const float* Wp = W + hh * FIN * FOUT + f;
    float acc[RPB];
#pragma unroll
    for (int r = 0; r < RPB; r++) acc[r] = 0.f;

    for (int i0 = 0; i0 < FIN; i0 += 16) {
        float wreg[16];
#pragma unroll
        for (int i = 0; i < 16; i++) wreg[i] = Wp[(i0 + i) * FOUT];
#pragma unroll
        for (int r = 0; r < RPB; r++) {
#pragma unroll
            for (int iq = 0; iq < 4; iq++) {
                float4 hv = *(const float4*)&h_s[r][i0 + iq * 4];
                acc[r] = fmaf(hv.x, wreg[iq * 4 + 0], acc[r]);
                acc[r] = fmaf(hv.y, wreg[iq * 4 + 1], acc[r]);
                acc[r] = fmaf(hv.z, wreg[iq * 4 + 2], acc[r]);
                acc[r] = fmaf(hv.w, wreg[iq * 4 + 3], acc[r]);
            }
        }
    }

    // fp16 store into tiled layout
    {
        const int jt = n0 >> 7, jc = n0 & 127;
        __half* dst = g_htT + ((size_t)(b * Hx + hh) * NTILES + jt) * HT_TILE_H + f * 128 + jc;
        __half2 p0 = __floats2half2_rn(acc[0], acc[1]);
        __half2 p1 = __floats2half2_rn(acc[2], acc[3]);
        __half2 p2 = __floats2half2_rn(acc[4], acc[5]);
        __half2 p3 = __floats2half2_rn(acc[6], acc[7]);
        uint4 u;
        u.x = *(uint32_t*)&p0; u.y = *(uint32_t*)&p1;
        u.z = *(uint32_t*)&p2; u.w = *(uint32_t*)&p3;
        *(uint4*)dst = u;
    }

#pragma unroll
    for (int r = 0; r < RPB; r++) {
        float ps = acc[r] * asrc, pd = acc[r] * adst;
#pragma unroll
        for (int off = 16; off > 0; off >>= 1) {
            ps += __shfl_down_sync(0xffffffffu, ps, off);
            pd += __shfl_down_sync(0xffffffffu, pd, off);
        }
        if (lane == 0) { red_s[r][hh][half][0] = ps; red_s[r][hh][half][1] = pd; }
    }
    __syncthreads();
    if (t < RPB * Hx) {
        int r = t >> 2, h2 = t & 3;
        g_esrcT[(b * Hx + h2) * Nx + n0 + r] = red_s[r][h2][0][0] + red_s[r][h2][1][0];
        g_edstT[(b * Hx + h2) * Nx + n0 + r] = red_s[r][h2][0][1] + red_s[r][h2][1][1];
    }
}

// ---------------------------------------------------------------------------
// Kernel 1b: per (b,h) max of e_dst (for fp16 overflow shift)
// ---------------------------------------------------------------------------
__global__ __launch_bounds__(256) void maxd_kernel()
{
    __shared__ float red[8];
    const int t = threadIdx.x;
    const float* p = g_edstT + (size_t)blockIdx.x * Nx;
    float m = -1e30f;
#pragma unroll
    for (int k = 0; k < 8; k++) m = fmaxf(m, p[t + 256 * k]);
#pragma unroll
    for (int off = 16; off > 0; off >>= 1)
        m = fmaxf(m, __shfl_xor_sync(0xffffffffu, m, off));
    if ((t & 31) == 0) red[t >> 5] = m;
    __syncthreads();
    if (t == 0) {
        float mm = red[0];
#pragma unroll
        for (int k = 1; k < 8; k++) mm = fmaxf(mm, red[k]);
        g_maxd[blockIdx.x] = mm;
    }
}

// ---------------------------------------------------------------------------
// Kernel 2: flash attention, mma.sync fp16 (m16n8k16). Block = (m128, h, b).
// ---------------------------------------------------------------------------
__global__ __launch_bounds__(256, 2) void gat_attn_mma(float* __restrict__ out)
{
    extern __shared__ char smraw[];
    __half* w_h = (__half*)smraw;
    __half* hs_h = (__half*)(smraw + WS_BYTES);
    float* rsum2 = (float*)(smraw + RS_OFF);
    uint32_t* w32 = (uint32_t*)w_h;
    uint32_t* h32 = (uint32_t*)hs_h;

    const int t = threadIdx.x, lane = t & 31, wid = t >> 5;
    const int b = blockIdx.z, hh = blockIdx.y, m0 = blockIdx.x * MT;
    const int mg = wid & 3, khalf = wid >> 2;
    const int gq = lane >> 2, tq = lane & 3;

    // producer mapping
    const int pm = t & 127;
    const int jhalf = t >> 7;
    const int jh = jhalf * 64;
    const float es = g_esrcT[(b * Hx + hh) * Nx + m0 + pm];
    const float maxd = g_maxd[b * Hx + hh];
    const float Cm = fmaxf(0.f, es + maxd);
    float rs = 0.f;
    const float* edp0 = g_edstT + (size_t)(b * Hx + hh) * Nx + jh;
    const __half* hsrc0 = g_htT + (size_t)(b * Hx + hh) * NTILES * HT_TILE_H;
    const uint32_t* bitrow = g_adjbits + (size_t)(m0 + pm) * (Nx / 32);

    float acc[2][8][4];
#pragma unroll
    for (int s = 0; s < 2; s++)
#pragma unroll
        for (int nt = 0; nt < 8; nt++)
#pragma unroll
            for (int i = 0; i < 4; i++) acc[s][nt][i] = 0.f;

    for (int jt = 0; jt < NTILES; jt++) {
        const int j0 = jt * JT;

        // ---- stage htT tile: dense fp16 -> padded smem, conflict-free ----
        {
            const uint4* src = (const uint4*)(hsrc0 + (size_t)jt * HT_TILE_H);
#pragma unroll
            for (int k = 0; k < 4; k++) {
                int idx = t + 256 * k;
                int row = idx >> 4, c = idx & 15;
                *(uint4*)&hs_h[row * TSH + c * 8] = src[idx];
            }
        }
        // ---- produce w tile: bits * exp(lrelu(es+ed) - Cm), fp16 ----
        {
            uint2 bw = *(const uint2*)&bitrow[(j0 + jh) >> 5];
            const float4* ep = (const float4*)(edp0 + j0);
#pragma unroll 2
            for (int q = 0; q < 8; q++) {
                uint32_t bits8 = ((q < 4 ? bw.x : bw.y) >> ((q * 8) & 31)) & 0xff;
                float4 e0 = ep[2 * q];
                float4 e1 = ep[2 * q + 1];
                float w[8];
                float ev;
                ev = es + e0.x; ev = fmaxf(ev, ALPHA * ev); w[0] = __expf(ev - Cm);
                ev = es + e0.y; ev = fmaxf(ev, ALPHA * ev); w[1] = __expf(ev - Cm);
                ev = es + e0.z; ev = fmaxf(ev, ALPHA * ev); w[2] = __expf(ev - Cm);
                ev = es + e0.w; ev = fmaxf(ev, ALPHA * ev); w[3] = __expf(ev - Cm);
                ev = es + e1.x; ev = fmaxf(ev, ALPHA * ev); w[4] = __expf(ev - Cm);
                ev = es + e1.y; ev = fmaxf(ev, ALPHA * ev); w[5] = __expf(ev - Cm);
                ev = es + e1.z; ev = fmaxf(ev, ALPHA * ev); w[6] = __expf(ev - Cm);
                ev = es + e1.w; ev = fmaxf(ev, ALPHA * ev); w[7] = __expf(ev - Cm);
#pragma unroll
                for (int i = 0; i < 8; i++) {
                    w[i] = (bits8 >> i) & 1 ? w[i] : 0.f;
                    rs += w[i];
                }
                __half2 p0 = __floats2half2_rn(w[0], w[1]);
                __half2 p1 = __floats2half2_rn(w[2], w[3]);
                __half2 p2 = __floats2half2_rn(w[4], w[5]);
                __half2 p3 = __floats2half2_rn(w[6], w[7]);
                uint4 u;
                u.x = *(uint32_t*)&p0; u.y = *(uint32_t*)&p1;
                u.z = *(uint32_t*)&p2; u.w = *(uint32_t*)&p3;
                *(uint4*)&w_h[pm * TSH + jh + q * 8] = u;
            }
        }
        __syncthreads();

        // ---- consume: 4 chunks of k16 over this warp's k half ----
#pragma unroll
        for (int ch = 0; ch < 4; ch++) {
            const int kb2 = khalf * 32 + ch * 8;    // b32 offset within row
            uint32_t afr[2][4];
#pragma unroll
            for (int s = 0; s < 2; s++) {
                const int r0 = (mg * 32 + s * 16 + gq) * TSH32 + kb2 + tq;
                afr[s][0] = w32[r0];
                afr[s][1] = w32[r0 + 8 * TSH32];
                afr[s][2] = w32[r0 + 4];
                afr[s][3] = w32[r0 + 8 * TSH32 + 4];
            }
#pragma unroll
            for (int nt = 0; nt < 8; nt++) {
                const int fb = (nt * 8 + gq) * TSH32 + kb2 + tq;
                uint32_t b0 = h32[fb];
                uint32_t b1 = h32[fb + 4];
#pragma unroll
                for (int s = 0; s < 2; s++) {
                    asm volatile(
                        "mma.sync.aligned.m16n8k16.row.col.f32.f16.f16.f32 "
                        "{%0,%1,%2,%3},{%4,%5,%6,%7},{%8,%9},{%0,%1,%2,%3};"
                        : "+f"(acc[s][nt][0]), "+f"(acc[s][nt][1]),
                          "+f"(acc[s][nt][2]), "+f"(acc[s][nt][3])
                        : "r"(afr[s][0]), "r"(afr[s][1]), "r"(afr[s][2]), "r"(afr[s][3]),
                          "r"(b0), "r"(b1));
                }
            }
        }
        __syncthreads();
    }

    // ---- row sums ----
    rsum2[pm * 2 + jhalf] = rs;

    // ---- k-split partials (reuse w region) ----
    float* red = (float*)smraw;
    if (khalf == 1) {
#pragma unroll
        for (int s = 0; s < 2; s++)
#pragma unroll
            for (int nt = 0; nt < 8; nt++)
#pragma unroll
                for (int i = 0; i < 4; i++)
                    red[(mg * 32 + lane) * 65 + s * 32 + nt * 4 + i] = acc[s][nt][i];
    }
    __syncthreads();

    if (khalf == 0) {
        const float* rp = &red[(mg * 32 + lane) * 65];
#pragma unroll
        for (int s = 0; s < 2; s++) {
            const int mrow = mg * 32 + s * 16 + gq;
            const float inv0 = 1.f / (rsum2[mrow * 2] + rsum2[mrow * 2 + 1]);
            const float inv1 = 1.f / (rsum2[(mrow + 8) * 2] + rsum2[(mrow + 8) * 2 + 1]);
            float* op0 = out + (size_t)(b * Nx + m0 + mrow) * (Hx * FOUT) + hh * FOUT;
            float* op1 = op0 + (size_t)8 * (Hx * FOUT);
#pragma unroll
            for (int nt = 0; nt < 8; nt++) {
                float2 v0, v1;
                v0.x = (acc[s][nt][0] + rp[s * 32 + nt * 4 + 0]) * inv0;
                v0.y = (acc[s][nt][1] + rp[s * 32 + nt * 4 + 1]) * inv0;
                v1.x = (acc[s][nt][2] + rp[s * 32 + nt * 4 + 2]) * inv1;
                v1.y = (acc[s][nt][3] + rp[s * 32 + nt * 4 + 3]) * inv1;
                const int col = nt * 8 + 2 * tq;
                *(float2*)(op0 + col) = v0;
                *(float2*)(op1 + col) = v1;
            }
        }
    }
}

extern "C" void kernel_launch(void* const* d_in, const int* in_sizes, int n_in,
                              void* d_out, int out_size) {
    (void)in_sizes; (void)n_in; (void)out_size;
    const float* h   = (const float*)d_in[0];
    const float* adj = (const float*)d_in[1];
    const float* W   = (const float*)d_in[2];
    const float* a   = (const float*)d_in[3];
    float* out = (float*)d_out;

    cudaFuncSetAttribute(gat_attn_mma, cudaFuncAttributeMaxDynamicSharedMemorySize, SM_TOTAL);

    adj_bits_kernel<<<512, 256>>>(adj);
    gat_proj_kernel<<<(Bx * Nx) / RPB, 256>>>(h, W, a);
    maxd_kernel<<<Bx * Hx, 256>>>();
    dim3 grid(Nx / MT, Hx, Bx);
    gat_attn_mma<<<grid, 256, SM_TOTAL>>>(out);
}

// round 7
// speedup vs baseline: 6.7890x; 1.1993x over previous
#include <cuda_runtime.h>
#include <cuda_fp16.h>
#include <cstdint>

// B=4, N=2048, F_in=128, F_out=64, H=4
#define Bx 4
#define Nx 2048
#define FIN 128
#define FOUT 64
#define Hx 4
#define ALPHA 0.2f
#define RPB 16

#define MT 128
#define JT 128
#define NTILES (Nx / JT)
#define TSH 136                 // halves per smem B row
#define TSH32 (TSH / 2)         // 68 u32 per row
#define HT_TILE_H (64 * 128)    // halves per (b,h,jt) htT tile (dense)

// Scratch
__device__ __half g_htT[(size_t)Bx * Hx * NTILES * HT_TILE_H];   // 4 MB
__device__ float g_esrcT[Bx * Hx * Nx];
__device__ float g_edstT[Bx * Hx * Nx];
__device__ uint32_t g_adjbits[Nx * (Nx / 32)];                   // 512 KB
__device__ float g_maxd[Bx * Hx];

// attn smem: hs B tile 72 rows x 136 halves, ed 128 f32, bits 128x4 u32
#define ED_OFF 19584
#define BITS_OFF (ED_OFF + 512)
#define SM_TOTAL (BITS_OFF + 2048)      // 22144 B

__device__ __forceinline__ float ex2f(float x) {
    float r;
    asm("ex2.approx.ftz.f32 %0, %1;" : "=f"(r) : "f"(x));
    return r;
}

// ---------------------------------------------------------------------------
// Kernel 1: projection -> g_htT (fp16, tiled [64 f][128 j]), e_src/e_dst fp32
// ---------------------------------------------------------------------------
__global__ __launch_bounds__(256) void gat_proj_kernel(
    const float* __restrict__ h, const float* __restrict__ W, const float* __restrict__ a)
{
    __shared__ float h_s[RPB][FIN];
    __shared__ float red_s[RPB][Hx][2][2];

    const int base = blockIdx.x * RPB;
    const int b = base >> 11, n0 = base & (Nx - 1);
    const int t = threadIdx.x;
    const int hh = t >> 6, f = t & 63;
    const int lane = t & 31, half = (t >> 5) & 1;

    ((float4*)h_s)[t] = ((const float4*)(h + (size_t)base * FIN))[t];
    ((float4*)h_s)[t + 256] = ((const float4*)(h + (size_t)base * FIN))[t + 256];
    const float asrc = a[hh * 2 * FOUT + f];
    const float adst = a[hh * 2 * FOUT + FOUT + f];
    __syncthreads();

    const float* Wp = W + hh * FIN * FOUT + f;
    float acc[RPB];
#pragma unroll
    for (int r = 0; r < RPB; r++) acc[r] = 0.f;

    for (int i0 = 0; i0 < FIN; i0 += 16) {
        float wreg[16];
#pragma unroll
        for (int i = 0; i < 16; i++) wreg[i] = Wp[(i0 + i) * FOUT];
#pragma unroll
        for (int r = 0; r < RPB; r++) {
#pragma unroll
            for (int iq = 0; iq < 4; iq++) {
                float4 hv = *(const float4*)&h_s[r][i0 + iq * 4];
                acc[r] = fmaf(hv.x, wreg[iq * 4 + 0], acc[r]);
                acc[r] = fmaf(hv.y, wreg[iq * 4 + 1], acc[r]);
                acc[r] = fmaf(hv.z, wreg[iq * 4 + 2], acc[r]);
                acc[r] = fmaf(hv.w, wreg[iq * 4 + 3], acc[r]);
            }
        }
    }

    // fp16 store, tiled layout: 16 consecutive n for this (h,f)
    {
        const int jt = n0 >> 7, jc = n0 & 127;
        __half* dst = g_htT + ((size_t)(b * Hx + hh) * NTILES + jt) * HT_TILE_H + f * 128 + jc;
        uint4 u0, u1;
        __half2 p;
        p = __floats2half2_rn(acc[0], acc[1]);  u0.x = *(uint32_t*)&p;
        p = __floats2half2_rn(acc[2], acc[3]);  u0.y = *(uint32_t*)&p;
        p = __floats2half2_rn(acc[4], acc[5]);  u0.z = *(uint32_t*)&p;
        p = __floats2half2_rn(acc[6], acc[7]);  u0.w = *(uint32_t*)&p;
        p = __floats2half2_rn(acc[8], acc[9]);  u1.x = *(uint32_t*)&p;
        p = __floats2half2_rn(acc[10], acc[11]); u1.y = *(uint32_t*)&p;
        p = __floats2half2_rn(acc[12], acc[13]); u1.z = *(uint32_t*)&p;
        p = __floats2half2_rn(acc[14], acc[15]); u1.w = *(uint32_t*)&p;
        *(uint4*)dst = u0;
        *(uint4*)(dst + 8) = u1;
    }

#pragma unroll
    for (int r = 0; r < RPB; r++) {
        float ps = acc[r] * asrc, pd = acc[r] * adst;
#pragma unroll
        for (int off = 16; off > 0; off >>= 1) {
            ps += __shfl_down_sync(0xffffffffu, ps, off);
            pd += __shfl_down_sync(0xffffffffu, pd, off);
        }
        if (lane == 0) { red_s[r][hh][half][0] = ps; red_s[r][hh][half][1] = pd; }
    }
    __syncthreads();
    if (t < RPB * Hx) {
        int r = t >> 2, h2 = t & 3;
        g_esrcT[(b * Hx + h2) * Nx + n0 + r] = red_s[r][h2][0][0] + red_s[r][h2][1][0];
        g_edstT[(b * Hx + h2) * Nx + n0 + r] = red_s[r][h2][0][1] + red_s[r][h2][1][1];
    }
}

// ---------------------------------------------------------------------------
// Kernel 2: pack adj bits; blocks 0..15 also compute per-(b,h) max e_dst.
// Must run AFTER proj (reads g_edstT).
// ---------------------------------------------------------------------------
__global__ __launch_bounds__(256) void adjbits_maxd_kernel(const float* __restrict__ adj)
{
    const int gw = (blockIdx.x * 256 + threadIdx.x) >> 5;
    const int lane = threadIdx.x & 31;
    const size_t base = (size_t)gw * 1024;
#pragma unroll 4
    for (int it = 0; it < 32; it++) {
        float v = adj[base + it * 32 + lane];
        uint32_t m = __ballot_sync(0xffffffffu, v > 0.5f);
        if (lane == 0) g_adjbits[gw * 32 + it] = m;
    }

    if (blockIdx.x < Bx * Hx) {
        __shared__ float red[8];
        const int t = threadIdx.x;
        const float* p = g_edstT + (size_t)blockIdx.x * Nx;
        float m = -1e30f;
#pragma unroll
        for (int k = 0; k < 8; k++) m = fmaxf(m, p[t + 256 * k]);
#pragma unroll
        for (int off = 16; off > 0; off >>= 1)
            m = fmaxf(m, __shfl_xor_sync(0xffffffffu, m, off));
        if (lane == 0) red[t >> 5] = m;
        __syncthreads();
        if (t == 0) {
            float mm = red[0];
#pragma unroll
            for (int k = 1; k < 8; k++) mm = fmaxf(mm, red[k]);
            g_maxd[blockIdx.x] = mm;
        }
    }
}

// ---------------------------------------------------------------------------
// Kernel 3: flash attention. A-fragments computed in registers; rs via
// ones-column MMA. 8 warps x (16 m-rows, full k). Block = (m128, h, b).
// ---------------------------------------------------------------------------
__global__ __launch_bounds__(256, 2) void gat_attn_mma(float* __restrict__ out)
{
    extern __shared__ char smraw[];
    uint32_t* h32 = (uint32_t*)smraw;
    float* ed_s = (float*)(smraw + ED_OFF);
    uint32_t* bits_s = (uint32_t*)(smraw + BITS_OFF);

    const int t = threadIdx.x, lane = t & 31, wid = t >> 5;
    const int gq = lane >> 2, tq = lane & 3;
    const int b = blockIdx.z, hh = blockIdx.y, m0 = blockIdx.x * MT;
    const int bh = b * Hx + hh;
    const int row0 = wid * 16 + gq, row1 = row0 + 8;
    const float L2E = 1.4426950408889634f;

    const float es0 = g_esrcT[bh * Nx + m0 + row0];
    const float es1 = g_esrcT[bh * Nx + m0 + row1];
    const float maxd = g_maxd[bh];
    const float c0 = fmaxf(0.f, es0 + maxd) * L2E;
    const float c1 = fmaxf(0.f, es1 + maxd) * L2E;
    const float P0 = es0 * L2E - c0, Q0 = ALPHA * es0 * L2E - c0;
    const float P1 = es1 * L2E - c1, Q1 = ALPHA * es1 * L2E - c1;

    // init B rows 64..71: row 64 = ones (first 128 halves), rest zeros
#pragma unroll
    for (int k = 0; k < 3; k++) {
        int i = t + 256 * k;
        if (i < 8 * TSH32) {
            int r = i / TSH32, cu = i % TSH32;
            h32[(64 + r) * TSH32 + cu] = (r == 0 && cu < 64) ? 0x3C003C00u : 0u;
        }
    }

    const __half* hsrc0 = g_htT + (size_t)bh * NTILES * HT_TILE_H;
    const uint32_t* bitbase = g_adjbits + (size_t)m0 * (Nx / 32);
    const float* edbase = g_edstT + (size_t)bh * Nx;

    float acc[9][4];
#pragma unroll
    for (int nt = 0; nt < 9; nt++)
#pragma unroll
        for (int i = 0; i < 4; i++) acc[nt][i] = 0.f;

    for (int jt = 0; jt < NTILES; jt++) {
        // ---- stage: B tile rows 0-63, ed, adj bits ----
        {
            const uint4* src = (const uint4*)(hsrc0 + (size_t)jt * HT_TILE_H);
#pragma unroll
            for (int k = 0; k < 4; k++) {
                int idx = t + 256 * k;
                int r = idx >> 4, c = idx & 15;
                *(uint4*)&h32[r * TSH32 + c * 4] = src[idx];
            }
        }
        if (t < 32) *(float4*)&ed_s[t * 4] = *(const float4*)&edbase[jt * 128 + t * 4];
        {
            int r = t >> 1, p = t & 1;
            *(uint2*)&bits_s[r * 4 + p * 2] =
                *(const uint2*)&bitbase[r * (Nx / 32) + jt * 4 + p * 2];
        }
        __syncthreads();

        const uint4 bw0 = *(const uint4*)&bits_s[row0 * 4];
        const uint4 bw1 = *(const uint4*)&bits_s[row1 * 4];

#pragma unroll
        for (int ch = 0; ch < 8; ch++) {
            const int k0 = ch * 16;
            const float2 eA = *(const float2*)&ed_s[k0 + 2 * tq];
            const float2 eB = *(const float2*)&ed_s[k0 + 2 * tq + 8];
            const uint32_t wrd0 = (ch >> 1) == 0 ? bw0.x : (ch >> 1) == 1 ? bw0.y
                                : (ch >> 1) == 2 ? bw0.z : bw0.w;
            const uint32_t wrd1 = (ch >> 1) == 0 ? bw1.x : (ch >> 1) == 1 ? bw1.y
                                : (ch >> 1) == 2 ? bw1.z : bw1.w;
            const uint32_t s0 = wrd0 >> (((ch & 1) << 4) + 2 * tq);
            const uint32_t s1 = wrd1 >> (((ch & 1) << 4) + 2 * tq);

            float arg, w00, w01, w08, w09, w10, w11, w18, w19;
            arg = fmaxf(fmaf(eA.x, L2E, P0), fmaf(eA.x, ALPHA * L2E, Q0));
            w00 = ex2f((s0 & 1u) ? arg : -10000.f);
            arg = fmaxf(fmaf(eA.y, L2E, P0), fmaf(eA.y, ALPHA * L2E, Q0));
            w01 = ex2f((s0 & 2u) ? arg : -10000.f);
            arg = fmaxf(fmaf(eB.x, L2E, P0), fmaf(eB.x, ALPHA * L2E, Q0));
            w08 = ex2f((s0 & 256u) ? arg : -10000.f);
            arg = fmaxf(fmaf(eB.y, L2E, P0), fmaf(eB.y, ALPHA * L2E, Q0));
            w09 = ex2f((s0 & 512u) ? arg : -10000.f);
            arg = fmaxf(fmaf(eA.x, L2E, P1), fmaf(eA.x, ALPHA * L2E, Q1));
            w10 = ex2f((s1 & 1u) ? arg : -10000.f);
            arg = fmaxf(fmaf(eA.y, L2E, P1), fmaf(eA.y, ALPHA * L2E, Q1));
            w11 = ex2f((s1 & 2u) ? arg : -10000.f);
            arg = fmaxf(fmaf(eB.x, L2E, P1), fmaf(eB.x, ALPHA * L2E, Q1));
            w18 = ex2f((s1 & 256u) ? arg : -10000.f);
            arg = fmaxf(fmaf(eB.y, L2E, P1), fmaf(eB.y, ALPHA * L2E, Q1));
            w19 = ex2f((s1 & 512u) ? arg : -10000.f);

            uint32_t afr0, afr1, afr2, afr3;
            __half2 hp;
            hp = __floats2half2_rn(w00, w01); afr0 = *(uint32_t*)&hp;
            hp = __floats2half2_rn(w10, w11); afr1 = *(uint32_t*)&hp;
            hp = __floats2half2_rn(w08, w09); afr2 = *(uint32_t*)&hp;
            hp = __floats2half2_rn(w18, w19); afr3 = *(uint32_t*)&hp;

#pragma unroll
            for (int nt = 0; nt < 9; nt++) {
                const int fb = (nt * 8 + gq) * TSH32 + ch * 8 + tq;
                uint32_t b0 = h32[fb];
                uint32_t b1 = h32[fb + 4];
                asm volatile(
                    "mma.sync.aligned.m16n8k16.row.col.f32.f16.f16.f32 "
                    "{%0,%1,%2,%3},{%4,%5,%6,%7},{%8,%9},{%0,%1,%2,%3};"
                    : "+f"(acc[nt][0]), "+f"(acc[nt][1]),
                      "+f"(acc[nt][2]), "+f"(acc[nt][3])
                    : "r"(afr0), "r"(afr1), "r"(afr2), "r"(afr3),
                      "r"(b0), "r"(b1));
            }
        }
        __syncthreads();
    }

    // ---- epilogue: rs from ones column (col 64 -> acc[8][0]/[2] at tq==0) ----
    const float rs0 = __shfl_sync(0xffffffffu, acc[8][0], lane & ~3);
    const float rs1 = __shfl_sync(0xffffffffu, acc[8][2], lane & ~3);
    const float inv0 = 1.f / rs0, inv1 = 1.f / rs1;
    float* op0 = out + (size_t)(b * Nx + m0 + row0) * (Hx * FOUT) + hh * FOUT;
    float* op1 = out + (size_t)(b * Nx + m0 + row1) * (Hx * FOUT) + hh * FOUT;
#pragma unroll
    for (int nt = 0; nt < 8; nt++) {
        float2 v0, v1;
        v0.x = acc[nt][0] * inv0; v0.y = acc[nt][1] * inv0;
        v1.x = acc[nt][2] * inv1; v1.y = acc[nt][3] * inv1;
        *(float2*)&op0[nt * 8 + 2 * tq] = v0;
        *(float2*)&op1[nt * 8 + 2 * tq] = v1;
    }
}

extern "C" void kernel_launch(void* const* d_in, const int* in_sizes, int n_in,
                              void* d_out, int out_size) {
    (void)in_sizes; (void)n_in; (void)out_size;
    const float* h   = (const float*)d_in[0];
    const float* adj = (const float*)d_in[1];
    const float* W   = (const float*)d_in[2];
    const float* a   = (const float*)d_in[3];
    float* out = (float*)d_out;

    cudaFuncSetAttribute(gat_attn_mma, cudaFuncAttributeMaxDynamicSharedMemorySize, SM_TOTAL);

    gat_proj_kernel<<<(Bx * Nx) / RPB, 256>>>(h, W, a);
    adjbits_maxd_kernel<<<512, 256>>>(adj);
    dim3 grid(Nx / MT, Hx, Bx);
    gat_attn_mma<<<grid, 256, SM_TOTAL>>>(out);
}